// round 12
// baseline (speedup 1.0000x reference)
#include <cuda_runtime.h>

// Gaussian splatting via tile-owned gather (8x8x16 tiles) with globally
// precomputed per-gaussian exp tables.
//  K0 (memset): zero per-tile counters.
//  K1 params: per-gaussian bbox -> packed params.
//  K2 scatter: 18 threads per gaussian, <=1 atomic each (full MLP via
//     occupancy); bucket entries {mnpack, gid}.
//  K3 tables: one thread per slot builds padded exp tables (coalesced STG).
//     Per gaussian: x[32] y[32] z[48] = 112 floats; x/y anchored mn-8,
//     z anchored mn-16; zeros outside bbox; intensity folded into z.
//  K4 accum: one 64-thread CTA per tile; window-gather tables into smem,
//     single barrier, BRANCHLESS scan with packed f32x2 FMAs (inactive
//     gaussians contribute exact zeros); volume written once (float4).

#define NTILES 16384                   // 32 x 32 x 16
#define CAP 64
#define NMAX 65536
#define TABW 112

__device__ int    d_counts[NTILES];
__device__ int2   d_bucket[NTILES * CAP];   // {mnpack, gid}
__device__ float4 d_params[2 * NMAX];       // [2g]={cx,cy,cz,inv2s2}; [2g+1]={I, mnpack, wpack, 0}
__device__ float  d_gtab[NMAX * TABW];

__device__ __forceinline__ void fma2(unsigned long long& d,
                                     unsigned long long a,
                                     unsigned long long b) {
    asm("fma.rn.f32x2 %0, %1, %2, %0;" : "+l"(d) : "l"(a), "l"(b));
}
__device__ __forceinline__ unsigned long long dup2(float x) {
    unsigned long long r;
    asm("mov.b64 %0, {%1, %1};" : "=l"(r) : "f"(x));
    return r;
}
__device__ __forceinline__ float2 unpack2(unsigned long long v) {
    float2 r;
    asm("mov.b64 {%0, %1}, %2;" : "=f"(r.x), "=f"(r.y) : "l"(v));
    return r;
}

__global__ void params_kernel(const float* __restrict__ centers,
                              const float* __restrict__ sigmas,
                              const float* __restrict__ intensities,
                              int n) {
    int g = blockIdx.x * blockDim.x + threadIdx.x;
    if (g >= n) return;

    float c3[3];
    c3[0] = __ldg(&centers[3 * g + 0]);
    c3[1] = __ldg(&centers[3 * g + 1]);
    c3[2] = __ldg(&centers[3 * g + 2]);
    const float sig   = __ldg(&sigmas[g]);
    const float inten = __ldg(&intensities[g]);

    const float cut    = 3.0f * sig * 255.0f;
    const float inv2s2 = 0.5f / (sig * sig);

    int mn[3], mx[3];
#pragma unroll
    for (int a = 0; a < 3; a++) {
        float cv = c3[a] * 255.0f;
        mn[a] = (int)floorf(fmaxf(cv - cut, 0.0f));
        mx[a] = (int)fminf(floorf(fminf(cv + cut, 255.0f)) + 1.0f, 256.0f);
    }

    int mnp = mn[0] | (mn[1] << 8) | (mn[2] << 16);
    int wp  = (mx[0] - mn[0]) | ((mx[1] - mn[1]) << 8) | ((mx[2] - mn[2]) << 16);

    d_params[2 * g + 0] = make_float4(c3[0], c3[1], c3[2], inv2s2);
    d_params[2 * g + 1] = make_float4(inten, __int_as_float(mnp), __int_as_float(wp), 0.0f);
}

// 18 threads per gaussian: slot s -> (dx, dy, dz) in 3x3x2.
__global__ void __launch_bounds__(256) scatter_kernel(int n) {
    int e = blockIdx.x * blockDim.x + threadIdx.x;
    int g = e / 18;
    if (g >= n) return;
    int s = e - g * 18;
    int dz = s & 1;
    int q  = s >> 1;          // 0..8
    int dx = q / 3;
    int dy = q - dx * 3;

    float4 p1 = d_params[2 * g + 1];
    int mnp = __float_as_int(p1.y);
    int wp  = __float_as_int(p1.z);
    int mnx = mnp & 255, mny = (mnp >> 8) & 255, mnz = (mnp >> 16) & 255;
    int wx  = wp & 255,  wy  = (wp >> 8) & 255,  wz  = (wp >> 16) & 255;

    int t0x = mnx >> 3, nx = ((mnx + wx - 1) >> 3) - t0x;
    int t0y = mny >> 3, ny = ((mny + wy - 1) >> 3) - t0y;
    int t0z = mnz >> 4, nz = ((mnz + wz - 1) >> 4) - t0z;

    if (dx <= nx && dy <= ny && dz <= nz) {
        int t = ((t0x + dx) << 9) | ((t0y + dy) << 4) | (t0z + dz);
        int slot = atomicAdd(&d_counts[t], 1);
        if (slot < CAP) d_bucket[t * CAP + slot] = make_int2(mnp, g);
    }
}

__global__ void table_kernel(int n) {
    int e = blockIdx.x * blockDim.x + threadIdx.x;
    int g = e / TABW;
    if (g >= n) return;
    int s = e - g * TABW;

    float4 p0 = d_params[2 * g + 0];
    float4 p1 = d_params[2 * g + 1];

    int a   = (s < 32) ? 0 : ((s < 64) ? 1 : 2);
    int i   = s - ((a == 0) ? 0 : ((a == 1) ? 32 : 64));
    int pad = (a == 2) ? 16 : 8;

    float c = (a == 0) ? p0.x : ((a == 1) ? p0.y : p0.z);
    int mnp = __float_as_int(p1.y);
    int wp  = __float_as_int(p1.z);
    int mn_a = (mnp >> (8 * a)) & 255;
    int w_a  = (wp  >> (8 * a)) & 255;

    float v = 0.0f;
    if ((unsigned)(i - pad) < (unsigned)w_a) {
        float d = (float)(mn_a - pad + i) * (1.0f / 255.0f) - c;
        v = __expf(-d * d * p0.w);
        if (a == 2) v *= p1.x;
    }
    d_gtab[e] = v;
}

__global__ void __launch_bounds__(64) accum_kernel(float* __restrict__ out) {
    const int t   = blockIdx.x;
    const int tid = threadIdx.x;
    const int ox = (t >> 9) << 3;
    const int oy = ((t >> 4) & 31) << 3;
    const int oz = (t & 15) << 4;

    __shared__ int2 sbk[CAP];
    __shared__ __align__(16) float sx[CAP * 8];
    __shared__ __align__(16) float sy[CAP * 8];
    __shared__ __align__(16) float sz[CAP * 16];

    int cnt = d_counts[t];
    if (cnt > CAP) cnt = CAP;
    const int bucket_base = t * CAP;

    for (int i = tid; i < cnt; i += 64)
        sbk[i] = d_bucket[bucket_base + i];
    __syncthreads();

    // Window gathers (indices guaranteed in-range by table padding).
    const int n8 = cnt * 8;
    for (int e = tid; e < n8; e += 64) {
        int g = e >> 3, i = e & 7;
        int2 bk = sbk[g];
        int base = bk.y * TABW;
        sx[e] = d_gtab[base + (ox - (bk.x & 255) + 8) + i];
    }
    for (int e = tid; e < n8; e += 64) {
        int g = e >> 3, i = e & 7;
        int2 bk = sbk[g];
        int base = bk.y * TABW;
        sy[e] = d_gtab[base + 32 + (oy - ((bk.x >> 8) & 255) + 8) + i];
    }
    const int n16 = cnt * 16;
    for (int e = tid; e < n16; e += 64) {
        int g = e >> 4, i = e & 15;
        int2 bk = sbk[g];
        int base = bk.y * TABW;
        sz[e] = d_gtab[base + 64 + (oz - ((bk.x >> 16) & 255) + 16) + i];
    }
    __syncthreads();

    const int xi = tid >> 3;
    const int yi = tid & 7;
    const float* sxp = &sx[xi];
    const float* syp = &sy[yi];

    unsigned long long acc2[8];
#pragma unroll
    for (int p = 0; p < 8; p++) acc2[p] = 0ULL;

    // Branchless scan: inactive gaussians multiply by exact 0.
#pragma unroll 4
    for (int g = 0; g < cnt; g++) {
        float exy = sxp[g * 8] * syp[g * 8];
        unsigned long long w2 = dup2(exy);
        const ulonglong2* ez = (const ulonglong2*)&sz[g * 16];
        ulonglong2 a = ez[0], b = ez[1], c = ez[2], d = ez[3];
        fma2(acc2[0], w2, a.x);
        fma2(acc2[1], w2, a.y);
        fma2(acc2[2], w2, b.x);
        fma2(acc2[3], w2, b.y);
        fma2(acc2[4], w2, c.x);
        fma2(acc2[5], w2, c.y);
        fma2(acc2[6], w2, d.x);
        fma2(acc2[7], w2, d.y);
    }

    const int addr = (ox + xi) * 65536 + (oy + yi) * 256 + oz;
#pragma unroll
    for (int q = 0; q < 4; q++) {
        float2 lo = unpack2(acc2[2 * q + 0]);
        float2 hi = unpack2(acc2[2 * q + 1]);
        *(float4*)&out[addr + 4 * q] = make_float4(lo.x, lo.y, hi.x, hi.y);
    }
}

extern "C" void kernel_launch(void* const* d_in, const int* in_sizes, int n_in,
                              void* d_out, int out_size) {
    const float* centers = (const float*)d_in[0];
    const float* sigmas = (const float*)d_in[1];
    const float* intensities = (const float*)d_in[2];
    float* out = (float*)d_out;
    const int n = in_sizes[1];

    void* counts_ptr = nullptr;
    cudaGetSymbolAddress(&counts_ptr, d_counts);
    cudaMemsetAsync(counts_ptr, 0, NTILES * sizeof(int), 0);

    params_kernel<<<(n + 255) / 256, 256>>>(centers, sigmas, intensities, n);
    scatter_kernel<<<(n * 18 + 255) / 256, 256>>>(n);
    table_kernel<<<(n * TABW + 255) / 256, 256>>>(n);
    accum_kernel<<<NTILES, 64>>>(out);
}